// round 8
// baseline (speedup 1.0000x reference)
#include <cuda_runtime.h>

// diff[K, N, D] = x[None, :, :] - centroid[:, None, :]
// N=65536, K=32, D=64, fp32. Store-roofline: 536 MB out.
// Locked: KG=4 (gridDim.y=8), THREADS=256, ILP=1.
// Store-policy sweep: default -> 92.9us (L2 dirty thrash), .cs -> 76.3us.
// This round: .wt (write-through) — minimal L2 residency for the write
// stream. Tests whether "less L2 for writes" is monotone or U-shaped.

#define N_PTS 65536
#define K_CENT 32
#define D_DIM 64
#define D4 (D_DIM / 4)            // 16 float4 per row
#define KG 4                      // k's per CTA
#define KY (K_CENT / KG)          // gridDim.y = 8
#define CENT_F4 (KG * D4)         // 64 float4 = 1 KB staged per CTA
#define THREADS 256

__global__ void __launch_bounds__(THREADS, 8)
kmeans_diff_kernel(const float4* __restrict__ x,
                   const float4* __restrict__ cent,
                   float4* __restrict__ out) {
    __shared__ float4 sc[CENT_F4];

    const int k0 = blockIdx.y * KG;

    // Stage this CTA's KG centroid rows (1 KB) into shared.
    for (int i = threadIdx.x; i < CENT_F4; i += blockDim.x)
        sc[i] = cent[k0 * D4 + i];
    __syncthreads();

    const unsigned idx = blockIdx.x * THREADS + threadIdx.x;  // [0, N*D/4)
    const unsigned d4 = idx & (D4 - 1);

    const float4 xv = x[idx];  // DRAM first wave, L2 hit afterwards

    const size_t plane = (size_t)N_PTS * D4;  // float4 per k-plane
    float4* o = out + (size_t)k0 * plane + idx;

#pragma unroll
    for (int kk = 0; kk < KG; kk++) {
        const float4 c = sc[kk * D4 + d4];
        float4 r;
        r.x = xv.x - c.x;
        r.y = xv.y - c.y;
        r.z = xv.z - c.z;
        r.w = xv.w - c.w;
        __stwt(o, r);            // write-through: bypass L2 residency
        o += plane;
    }
}

extern "C" void kernel_launch(void* const* d_in, const int* in_sizes, int n_in,
                              void* d_out, int out_size) {
    const float4* x    = (const float4*)d_in[0];   // [N, D] fp32
    const float4* cent = (const float4*)d_in[1];   // [K, D] fp32
    float4* out        = (float4*)d_out;           // [K, N, D] fp32

    const int total_f4 = N_PTS * D4;               // 1,048,576
    dim3 grid(total_f4 / THREADS, KY);             // (4096, 8)
    kmeans_diff_kernel<<<grid, THREADS>>>(x, cent, out);
}

// round 9
// speedup vs baseline: 1.2196x; 1.2196x over previous
#include <cuda_runtime.h>

// diff[K, N, D] = x[None, :, :] - centroid[:, None, :]
// N=65536, K=32, D=64, fp32. Store-roofline: 536 MB out.
// Locked from sweeps: KG=4 (gridDim.y=8), ILP=1, __stcs stores.
//   KG: 32->81.9, 8->78.0, 4->76.3, 2->77.1
//   ILP=2: regressed (R2, R6).  Policy: default 92.9, .cs 76.3, .wt 94.2.
// Final probe: THREADS 256 -> 512 (fewer CTAs/barriers, coarser waves).

#define N_PTS 65536
#define K_CENT 32
#define D_DIM 64
#define D4 (D_DIM / 4)            // 16 float4 per row
#define KG 4                      // k's per CTA
#define KY (K_CENT / KG)          // gridDim.y = 8
#define CENT_F4 (KG * D4)         // 64 float4 = 1 KB staged per CTA
#define THREADS 512

__global__ void __launch_bounds__(THREADS, 4)
kmeans_diff_kernel(const float4* __restrict__ x,
                   const float4* __restrict__ cent,
                   float4* __restrict__ out) {
    __shared__ float4 sc[CENT_F4];

    const int k0 = blockIdx.y * KG;

    // Stage this CTA's KG centroid rows (1 KB) into shared.
    for (int i = threadIdx.x; i < CENT_F4; i += blockDim.x)
        sc[i] = cent[k0 * D4 + i];
    __syncthreads();

    const unsigned idx = blockIdx.x * THREADS + threadIdx.x;  // [0, N*D/4)
    const unsigned d4 = idx & (D4 - 1);

    const float4 xv = x[idx];  // DRAM first wave, L2 hit afterwards

    const size_t plane = (size_t)N_PTS * D4;  // float4 per k-plane
    float4* o = out + (size_t)k0 * plane + idx;

#pragma unroll
    for (int kk = 0; kk < KG; kk++) {
        const float4 c = sc[kk * D4 + d4];
        float4 r;
        r.x = xv.x - c.x;
        r.y = xv.y - c.y;
        r.z = xv.z - c.z;
        r.w = xv.w - c.w;
        __stcs(o, r);            // evict-first: proven optimal policy
        o += plane;
    }
}

extern "C" void kernel_launch(void* const* d_in, const int* in_sizes, int n_in,
                              void* d_out, int out_size) {
    const float4* x    = (const float4*)d_in[0];   // [N, D] fp32
    const float4* cent = (const float4*)d_in[1];   // [K, D] fp32
    float4* out        = (float4*)d_out;           // [K, N, D] fp32

    const int total_f4 = N_PTS * D4;               // 1,048,576
    dim3 grid(total_f4 / THREADS, KY);             // (2048, 8)
    kmeans_diff_kernel<<<grid, THREADS>>>(x, cent, out);
}

// round 10
// speedup vs baseline: 1.2304x; 1.0088x over previous
#include <cuda_runtime.h>

// diff[K, N, D] = x[None, :, :] - centroid[:, None, :]
// N=65536, K=32, D=64, fp32. Store-roofline: 536 MB out.
// (streams, MLP) matrix: (32,32)=81.9 (8,8)=78.0 (4,4)=76.3 (2,2)=77.1
//                        (4,8)=78.6.  Last untested cell: (2,4).
// KG=2 planes per CTA + two x float4 per thread -> 2 concurrent write
// streams chip-wide with per-thread store MLP kept at 4. __stcs proven
// optimal (default 92.9, .wt 94.2).

#define N_PTS 65536
#define K_CENT 32
#define D_DIM 64
#define D4 (D_DIM / 4)            // 16 float4 per row
#define KG 2                      // k's per CTA
#define KY (K_CENT / KG)          // gridDim.y = 16
#define CENT_F4 (KG * D4)         // 32 float4 = 512 B staged per CTA
#define THREADS 256

__global__ void __launch_bounds__(THREADS, 8)
kmeans_diff_kernel(const float4* __restrict__ x,
                   const float4* __restrict__ cent,
                   float4* __restrict__ out) {
    __shared__ float4 sc[CENT_F4];

    const int k0 = blockIdx.y * KG;

    // Stage this CTA's KG centroid rows into shared.
    for (int i = threadIdx.x; i < CENT_F4; i += blockDim.x)
        sc[i] = cent[k0 * D4 + i];
    __syncthreads();

    // Each CTA covers 2*THREADS consecutive float4 of x.
    const unsigned idx0 = blockIdx.x * (2 * THREADS) + threadIdx.x;
    const unsigned idx1 = idx0 + THREADS;
    const unsigned d4 = idx0 & (D4 - 1);   // same for idx1 (THREADS % D4 == 0)

    const float4 xv0 = x[idx0];            // L2-resident after first wave
    const float4 xv1 = x[idx1];

    const size_t plane = (size_t)N_PTS * D4;  // float4 per k-plane
    float4* o = out + (size_t)k0 * plane;

#pragma unroll
    for (int kk = 0; kk < KG; kk++) {
        const float4 c = sc[kk * D4 + d4];
        float4 r0, r1;
        r0.x = xv0.x - c.x; r0.y = xv0.y - c.y;
        r0.z = xv0.z - c.z; r0.w = xv0.w - c.w;
        r1.x = xv1.x - c.x; r1.y = xv1.y - c.y;
        r1.z = xv1.z - c.z; r1.w = xv1.w - c.w;
        __stcs(o + idx0, r0);
        __stcs(o + idx1, r1);
        o += plane;
    }
}

extern "C" void kernel_launch(void* const* d_in, const int* in_sizes, int n_in,
                              void* d_out, int out_size) {
    const float4* x    = (const float4*)d_in[0];   // [N, D] fp32
    const float4* cent = (const float4*)d_in[1];   // [K, D] fp32
    float4* out        = (float4*)d_out;           // [K, N, D] fp32

    const int total_f4 = N_PTS * D4;               // 1,048,576
    dim3 grid(total_f4 / (2 * THREADS), KY);       // (2048, 16)
    kmeans_diff_kernel<<<grid, THREADS>>>(x, cent, out);
}